// round 1
// baseline (speedup 1.0000x reference)
#include <cuda_runtime.h>
#include <stdint.h>

#define NN 16384
#define DD 32
#define WPR (NN / 32)   // 512 words per bitmask row

// 16384 * 512 words = 8,388,608 u32 = 32 MB. Zero-initialized at module load.
// The aggregate kernel zeroes every word it reads, so each launch sees a
// clean mask built by its own build pass (deterministic, graph-replay safe).
__device__ uint32_t g_bits[(size_t)NN * WPR];

__global__ void __launch_bounds__(256) build_kernel(const int* __restrict__ src,
                                                    const int* __restrict__ dst,
                                                    int E) {
    int e = blockIdx.x * blockDim.x + threadIdx.x;
    if (e >= E) return;
    int s = src[e];
    int d = dst[e];
    atomicOr(&g_bits[(size_t)s * WPR + (d >> 5)], 1u << (d & 31));
    atomicOr(&g_bits[(size_t)d * WPR + (s >> 5)], 1u << (s & 31));
}

__global__ void __launch_bounds__(256) agg_kernel(const float* __restrict__ x,
                                                  const float* __restrict__ W_agg,
                                                  const float* __restrict__ b_agg,
                                                  const float* __restrict__ W_upd,
                                                  const float* __restrict__ b_upd,
                                                  float* __restrict__ out) {
    __shared__ float WaggT[DD * DD];   // WaggT[d][c] = W_agg[c][d]
    __shared__ float WupdT[DD * DD];
    __shared__ float bsum[DD];

    int tid = threadIdx.x;
    for (int i = tid; i < DD * DD; i += blockDim.x) {
        int c = i >> 5, d = i & 31;
        WaggT[d * DD + c] = W_agg[i];
        WupdT[d * DD + c] = W_upd[i];
    }
    if (tid < DD) bsum[tid] = b_agg[tid] + b_upd[tid];
    __syncthreads();

    int warp = tid >> 5;
    int lane = tid & 31;
    int row  = blockIdx.x * 8 + warp;   // 2048 blocks * 8 warps = 16384 rows

    uint32_t* rowbits = g_bits + (size_t)row * WPR;

    // Coalesced load of the whole row's bitmask: lane + 32*k, k=0..15.
    uint32_t w[16];
#pragma unroll
    for (int k = 0; k < 16; k++) w[k] = rowbits[k * 32 + lane];
    // Clear for next launch (each word owned by exactly one lane).
#pragma unroll
    for (int k = 0; k < 16; k++) rowbits[k * 32 + lane] = 0u;

    // acc = messages[row][lane]
    float acc = 0.0f;
#pragma unroll
    for (int k = 0; k < 16; k++) {
        unsigned nz = __ballot_sync(0xffffffffu, w[k] != 0u);
        while (nz) {
            int sl = __ffs(nz) - 1;
            nz &= nz - 1;
            uint32_t ww = __shfl_sync(0xffffffffu, w[k], sl);
            int jbase = ((k << 5) + sl) << 5;   // first column covered by this word
            while (ww) {
                int b = __ffs(ww) - 1;
                ww &= ww - 1;
                // one 128B coalesced line per neighbor; x (2MB) is L2-resident
                acc += x[(size_t)(jbase + b) * DD + lane];
            }
        }
    }

    // Fused epilogue: out[row][lane] = sum_d msg[d]*W_agg[lane][d]
    //                               + sum_d x[row][d]*W_upd[lane][d] + b_agg+b_upd
    float xi = x[(size_t)row * DD + lane];
    float o  = bsum[lane];
#pragma unroll
    for (int d = 0; d < DD; d++) {
        float m  = __shfl_sync(0xffffffffu, acc, d);
        float xv = __shfl_sync(0xffffffffu, xi, d);
        o += m * WaggT[d * DD + lane] + xv * WupdT[d * DD + lane];
    }
    out[(size_t)row * DD + lane] = o;
}

extern "C" void kernel_launch(void* const* d_in, const int* in_sizes, int n_in,
                              void* d_out, int out_size) {
    const float* x     = (const float*)d_in[0];
    const int*   ei    = (const int*)d_in[1];     // [2, E]: row0=src, row1=dst
    const float* W_agg = (const float*)d_in[2];
    const float* b_agg = (const float*)d_in[3];
    const float* W_upd = (const float*)d_in[4];
    const float* b_upd = (const float*)d_in[5];
    float* out = (float*)d_out;

    int E = in_sizes[1] / 2;

    build_kernel<<<(E + 255) / 256, 256>>>(ei, ei + E, E);
    agg_kernel<<<NN / 8, 256>>>(x, W_agg, b_agg, W_upd, b_upd, out);
}